// round 15
// baseline (speedup 1.0000x reference)
#include <cuda_runtime.h>
#include <cuda_bf16.h>
#include <cstdint>
#include <cstddef>

// Problem constants
#define S_DIM 64
#define B_DIM 4
#define N_DIM 256
#define D_MODEL 256
#define HEADS 8
#define DHEAD 32
#define INNER 256
#define QKV_COLS 768
#define M_TOTAL (S_DIM * B_DIM * N_DIM)   // 65536
#define SCALE 0.17677669529663687f
#define KS 512            // stored split width: [hi(256) | lo(256)]
#define NCHUNKS 12        // logical K' = 768 = 12 x 64

typedef unsigned long long ull;

// ---- mma / ldmatrix / cp.async helpers (baseline PTX, sm_80+) ----
__device__ __forceinline__ uint32_t smem_u32(const void* p) {
    uint32_t a;
    asm("{ .reg .u64 t; cvta.to.shared.u64 t, %1; cvt.u32.u64 %0, t; }"
        : "=r"(a) : "l"(p));
    return a;
}
__device__ __forceinline__ void ldm4(uint32_t* r, uint32_t addr) {
    asm volatile("ldmatrix.sync.aligned.m8n8.x4.shared.b16 {%0,%1,%2,%3}, [%4];"
        : "=r"(r[0]), "=r"(r[1]), "=r"(r[2]), "=r"(r[3]) : "r"(addr));
}
__device__ __forceinline__ void mma16816(float* c, const uint32_t* a,
                                         uint32_t b0, uint32_t b1) {
    asm volatile("mma.sync.aligned.m16n8k16.row.col.f32.bf16.bf16.f32 "
        "{%0,%1,%2,%3}, {%4,%5,%6,%7}, {%8,%9}, {%0,%1,%2,%3};"
        : "+f"(c[0]), "+f"(c[1]), "+f"(c[2]), "+f"(c[3])
        : "r"(a[0]), "r"(a[1]), "r"(a[2]), "r"(a[3]), "r"(b0), "r"(b1));
}
__device__ __forceinline__ void cp16(uint32_t s, const void* g) {
    asm volatile("cp.async.cg.shared.global [%0], [%1], 16;" :: "r"(s), "l"(g));
}
__device__ __forceinline__ void cp_commit() {
    asm volatile("cp.async.commit_group;" ::: "memory");
}
template <int N>
__device__ __forceinline__ void cp_wait() {
    asm volatile("cp.async.wait_group %0;" :: "n"(N) : "memory");
}
// pack two f32 into bf16x2: low half = lo arg, high half = hi arg
__device__ __forceinline__ uint32_t packbf(float lo, float hi) {
    uint32_t r;
    asm("cvt.rn.bf16x2.f32 %0, %1, %2;" : "=r"(r) : "f"(hi), "f"(lo));
    return r;
}
__device__ __forceinline__ float bf_lo(uint32_t u) { return __uint_as_float(u << 16); }
__device__ __forceinline__ float bf_hi(uint32_t u) { return __uint_as_float(u & 0xffff0000u); }

// Scratch (allocation-free rule: __device__ globals)
__device__ float g_qkv[(size_t)M_TOTAL * QKV_COLS];            // 192 MB
__device__ __nv_bfloat16 g_abf[(size_t)M_TOTAL * KS];          // 67 MB (split A)
__device__ __nv_bfloat16 g_wqt[(size_t)QKV_COLS * KS];         // W_qkv^T split
__device__ __nv_bfloat16 g_wot[(size_t)D_MODEL * KS];          // W_out^T split
__device__ unsigned g_maskpack[S_DIM][N_DIM][8];

// ---------------------------------------------------------------------------
// Prep kernels
// ---------------------------------------------------------------------------
__global__ void pack_mask_kernel(const int* __restrict__ mask) {
    const int s = blockIdx.x, i = threadIdx.x;
    const int* p = mask + ((size_t)s * N_DIM + i) * N_DIM;
    #pragma unroll
    for (int c = 0; c < 8; c++) {
        unsigned bits = 0;
        #pragma unroll 8
        for (int bb = 0; bb < 32; bb++)
            bits |= (unsigned)(p[c * 32 + bb] != 0) << bb;
        g_maskpack[s][i][c] = bits;
    }
}

// split fp32 [rows,256] -> bf16 [rows, hi256|lo256], grid-stride float4
__global__ __launch_bounds__(256)
void split_a_kernel(const float* __restrict__ src,
                    __nv_bfloat16* __restrict__ dst) {
    const int nf4 = M_TOTAL * 64;   // total float4s
    for (int idx = blockIdx.x * blockDim.x + threadIdx.x; idx < nf4;
         idx += gridDim.x * blockDim.x) {
        int row = idx >> 6;
        int c4 = (idx & 63) * 4;
        float4 v = *(const float4*)(src + (size_t)row * 256 + c4);
        uint32_t h0 = packbf(v.x, v.y);
        uint32_t h1 = packbf(v.z, v.w);
        uint32_t l0 = packbf(v.x - bf_lo(h0), v.y - bf_hi(h0));
        uint32_t l1 = packbf(v.z - bf_lo(h1), v.w - bf_hi(h1));
        __nv_bfloat16* d = dst + (size_t)row * KS;
        *(uint2*)(d + c4) = make_uint2(h0, h1);
        *(uint2*)(d + 256 + c4) = make_uint2(l0, l1);
    }
}

// W [256 (k), Ncols] fp32 -> Wt bf16 [Ncols (n)][hi256|lo256].
// For the QKV weight (Ncols==768), q columns (n<256) are pre-scaled by SCALE.
__global__ void split_w_kernel(const float* __restrict__ W,
                               __nv_bfloat16* __restrict__ Wt, int Ncols) {
    const int n = blockIdx.x;
    const int k = threadIdx.x;
    float w = W[(size_t)k * Ncols + n];
    if (Ncols == QKV_COLS && n < 256) w *= SCALE;
    __nv_bfloat16 hi = __float2bfloat16_rn(w);
    __nv_bfloat16 lo = __float2bfloat16_rn(w - __bfloat162float(hi));
    __nv_bfloat16* d = Wt + (size_t)n * KS;
    d[k] = hi; d[256 + k] = lo;
}

// ---------------------------------------------------------------------------
// Tensor-core GEMM: C = A' x B'^T, logical K' = 768, 3-stage cp.async pipe.
// ---------------------------------------------------------------------------
#define GEMM_SMEM (96 * 1024)   // 3 x (A 16K + B 16K)

__constant__ int c_cmapA[NCHUNKS] = {0,1,2,3,4,5,6,7,0,1,2,3};
__constant__ int c_cmapB[NCHUNKS] = {0,1,2,3,0,1,2,3,4,5,6,7};

__global__ __launch_bounds__(256, 2)
void gemm_mma_kernel(const __nv_bfloat16* __restrict__ A,
                     const __nv_bfloat16* __restrict__ Bt,
                     float* __restrict__ C, const float* __restrict__ bias,
                     int Ntot) {
    extern __shared__ __align__(1024) char smx[];
    const uint32_t sb = smem_u32(smx);
    const int tid = threadIdx.x;
    const int lane = tid & 31, w = tid >> 5;
    const int bx = blockIdx.x, by = blockIdx.y;
    const size_t arow0 = (size_t)by * 128;
    const size_t brow0 = (size_t)bx * 128;
    const int mrow = (w & 3) * 32;
    const int ncol = (w >> 2) * 64;

    uint32_t aoff[2], boff[4];
    const uint32_t khA = (lane >> 4) * 16;
    const uint32_t khB = ((lane >> 3) & 1) * 16;
    #pragma unroll
    for (int mt = 0; mt < 2; mt++) {
        uint32_t rp = (uint32_t)(mrow + mt * 16 + (lane & 15)) * 128;
        aoff[mt] = rp ^ ((rp >> 3) & 0x70);
    }
    #pragma unroll
    for (int nt = 0; nt < 4; nt++) {
        uint32_t n = ncol + nt * 16 + (lane & 7) + ((lane >> 4) << 3);
        uint32_t rp = n * 128;
        boff[nt] = rp ^ ((rp >> 3) & 0x70);
    }

    const char* Abase = (const char*)(A + arow0 * KS);
    const char* Bbase = (const char*)(Bt + brow0 * KS);
    const int crow = tid >> 1;
    const int cpart = (tid & 1) * 4;

    float acc[2][8][4];
    #pragma unroll
    for (int mt = 0; mt < 2; mt++)
        #pragma unroll
        for (int nt = 0; nt < 8; nt++)
            #pragma unroll
            for (int q = 0; q < 4; q++) acc[mt][nt][q] = 0.0f;

    auto issue = [&](int c, int buf) {
        const char* Ac = Abase + c_cmapA[c] * 128;
        const char* Bc = Bbase + c_cmapB[c] * 128;
        uint32_t sA = sb + buf * 16384;
        uint32_t sB = sb + 49152 + buf * 16384;
        #pragma unroll
        for (int p = 0; p < 4; p++) {
            uint32_t off = (uint32_t)crow * 128 + (cpart + p) * 16;
            uint32_t sw = off ^ ((off >> 3) & 0x70);
            cp16(sA + sw, Ac + (size_t)crow * (KS * 2) + (cpart + p) * 16);
            cp16(sB + sw, Bc + (size_t)crow * (KS * 2) + (cpart + p) * 16);
        }
        cp_commit();
    };

    issue(0, 0);
    issue(1, 1);
    for (int c = 0; c < NCHUNKS; c++) {
        const int buf = c % 3;
        if (c + 2 < NCHUNKS) {
            issue(c + 2, (c + 2) % 3);
            cp_wait<2>();
        } else if (c + 1 < NCHUNKS) {
            cp_wait<1>();
        } else {
            cp_wait<0>();
        }
        __syncthreads();

        const uint32_t sA = sb + buf * 16384;
        const uint32_t sB = sb + 49152 + buf * 16384;
        #pragma unroll
        for (int ks = 0; ks < 4; ks++) {
            uint32_t a[2][4], b[4][4];
            #pragma unroll
            for (int mt = 0; mt < 2; mt++)
                ldm4(a[mt], sA + (aoff[mt] ^ (ks * 32 + khA)));
            #pragma unroll
            for (int nt = 0; nt < 4; nt++)
                ldm4(b[nt], sB + (boff[nt] ^ (ks * 32 + khB)));
            #pragma unroll
            for (int mt = 0; mt < 2; mt++)
                #pragma unroll
                for (int nt = 0; nt < 4; nt++) {
                    mma16816(acc[mt][2 * nt + 0], a[mt], b[nt][0], b[nt][1]);
                    mma16816(acc[mt][2 * nt + 1], a[mt], b[nt][2], b[nt][3]);
                }
        }
        __syncthreads();
    }

    const int g = lane >> 2, t4 = lane & 3;
    #pragma unroll
    for (int mt = 0; mt < 2; mt++) {
        #pragma unroll
        for (int sub = 0; sub < 2; sub++) {
            size_t row = arow0 + mrow + mt * 16 + g + sub * 8;
            float* Cr = C + row * Ntot + brow0;
            #pragma unroll
            for (int nt = 0; nt < 8; nt++) {
                int col = ncol + nt * 8 + 2 * t4;
                float2 v = make_float2(acc[mt][nt][sub * 2 + 0],
                                       acc[mt][nt][sub * 2 + 1]);
                if (bias) {
                    v.x += __ldg(bias + brow0 + col);
                    v.y += __ldg(bias + brow0 + col + 1);
                }
                *(float2*)(Cr + col) = v;
            }
        }
    }
}

// ---------------------------------------------------------------------------
// MMA flash-attention: one CTA per (s,b,h), 512 threads = 16 warps x 16 rows.
// QK and PV mma streams interleaved across 4 accumulators (ILP fix).
// ---------------------------------------------------------------------------
#define AQ_OFF 0
#define AK_OFF 32768
#define AV_OFF 65536
#define AM_OFF 98304
#define ATTN_SMEM_BYTES (98304 + 8192)

__global__ __launch_bounds__(512, 1)
void attn_mma_kernel(const float* __restrict__ qkv,
                     __nv_bfloat16* __restrict__ outsp) {
    extern __shared__ __align__(1024) char smx[];
    const uint32_t sb = smem_u32(smx);
    const int tid = threadIdx.x;
    const int lane = tid & 31, w = tid >> 5;   // w = 0..15
    const int g = lane >> 2, t4 = lane & 3;
    const int h = blockIdx.x, b = blockIdx.y, s = blockIdx.z;
    const size_t base = ((size_t)(s * B_DIM + b) * N_DIM) * QKV_COLS;

    // ---- load + split phase (2048 work items over 512 threads) ----
    unsigned* sM = (unsigned*)(smx + AM_OFF);
    #pragma unroll
    for (int t = 0; t < 4; t++) {
        int idx = t * 512 + tid;
        int j = idx >> 3, d4 = (idx & 7) * 4;
        const float* rowp = qkv + base + (size_t)j * QKV_COLS + h * DHEAD;
        float4 qv = *(const float4*)(rowp + d4);
        float4 kv = *(const float4*)(rowp + INNER + d4);
        float qs[4] = {qv.x, qv.y, qv.z, qv.w};
        float kk[4] = {kv.x, kv.y, kv.z, kv.w};
        uint32_t qh[2], ql[2], kh[2], kl[2];
        #pragma unroll
        for (int p = 0; p < 2; p++) {
            float a0 = qs[2 * p], a1 = qs[2 * p + 1];
            uint32_t uh = packbf(a0, a1);
            qh[p] = uh;
            ql[p] = packbf(a0 - bf_lo(uh), a1 - bf_hi(uh));
            float b0 = kk[2 * p], b1 = kk[2 * p + 1];
            uint32_t vh = packbf(b0, b1);
            kh[p] = vh;
            kl[p] = packbf(b0 - bf_lo(vh), b1 - bf_hi(vh));
        }
        uint32_t offh = (uint32_t)j * 128 + d4 * 2;
        uint32_t offl = offh + 64;
        uint32_t swh = offh ^ ((offh >> 3) & 0x70);
        uint32_t swl = offl ^ ((offl >> 3) & 0x70);
        *(uint2*)(smx + AQ_OFF + swh) = make_uint2(qh[0], qh[1]);
        *(uint2*)(smx + AQ_OFF + swl) = make_uint2(ql[0], ql[1]);
        *(uint2*)(smx + AK_OFF + swh) = make_uint2(kh[0], kh[1]);
        *(uint2*)(smx + AK_OFF + swl) = make_uint2(kl[0], kl[1]);
        float4 vv = *(const float4*)(rowp + 2 * INNER + d4);
        float ve[4] = {vv.x, vv.y, vv.z, vv.w};
        #pragma unroll
        for (int e = 0; e < 4; e++) {
            int d = d4 + e;
            __nv_bfloat16 hi = __float2bfloat16_rn(ve[e]);
            __nv_bfloat16 lo = __float2bfloat16_rn(ve[e] - __bfloat162float(hi));
            uint32_t oh = (uint32_t)d * 512 + j * 2;
            uint32_t ol = (uint32_t)(d + 32) * 512 + j * 2;
            *(__nv_bfloat16*)(smx + AV_OFF + (oh ^ (((oh >> 9) & 7) << 4))) = hi;
            *(__nv_bfloat16*)(smx + AV_OFF + (ol ^ (((ol >> 9) & 7) << 4))) = lo;
        }
        sM[idx] = g_maskpack[s][idx >> 3][idx & 7];
    }
    __syncthreads();

    const uint32_t khA = (lane >> 4) * 16;
    const uint32_t khB = ((lane >> 3) & 1) * 16;
    uint32_t qroff;
    {
        uint32_t rp = (uint32_t)(w * 16 + (lane & 15)) * 128;
        qroff = rp ^ ((rp >> 3) & 0x70);
    }
    uint32_t qf[4][4];
    #pragma unroll
    for (int kt = 0; kt < 4; kt++)
        ldm4(qf[kt], sb + AQ_OFF + (qroff ^ (kt * 32 + khA)));
    uint32_t vroffh[2], vroffl[2];
    #pragma unroll
    for (int dn = 0; dn < 2; dn++) {
        uint32_t nh = dn * 16 + (lane & 7) + ((lane >> 4) << 3);
        uint32_t rph = nh * 512;
        vroffh[dn] = rph ^ (((rph >> 9) & 7) << 4);
        uint32_t rpl = (nh + 32) * 512;
        vroffl[dn] = rpl ^ (((rpl >> 9) & 7) << 4);
    }

    float oacc[4][4];
    #pragma unroll
    for (int nt = 0; nt < 4; nt++)
        #pragma unroll
        for (int q = 0; q < 4; q++) oacc[nt][q] = 0.0f;
    float lsum[2] = {0.0f, 0.0f};

    const int KPA[6] = {0, 1, 2, 3, 0, 1};
    const int KPB[6] = {0, 1, 0, 1, 2, 3};

    for (int jt = 0; jt < 4; jt++) {
        const int j0 = jt * 64;
        float sfrag[8][4];
        #pragma unroll
        for (int nt = 0; nt < 8; nt++)
            #pragma unroll
            for (int q = 0; q < 4; q++) sfrag[nt][q] = 0.0f;

        // ---- S = Q K^T : nt pairs, pp outer -> 4-way accumulator ILP ----
        #pragma unroll
        for (int ntp = 0; ntp < 2; ntp++) {
            uint32_t kb[2][4][4];
            #pragma unroll
            for (int nti = 0; nti < 2; nti++) {
                int nt = ntp * 2 + nti;
                uint32_t n = (uint32_t)(j0 + nt * 16 + (lane & 7) + ((lane >> 4) << 3));
                uint32_t rp = n * 128;
                uint32_t kro = rp ^ ((rp >> 3) & 0x70);
                #pragma unroll
                for (int kt = 0; kt < 4; kt++)
                    ldm4(kb[nti][kt], sb + AK_OFF + (kro ^ (kt * 32 + khB)));
            }
            #pragma unroll
            for (int pp = 0; pp < 6; pp++) {
                #pragma unroll
                for (int nti = 0; nti < 2; nti++) {
                    int nt = ntp * 2 + nti;
                    mma16816(sfrag[2 * nt + 0], qf[KPA[pp]],
                             kb[nti][KPB[pp]][0], kb[nti][KPB[pp]][1]);
                    mma16816(sfrag[2 * nt + 1], qf[KPA[pp]],
                             kb[nti][KPB[pp]][2], kb[nti][KPB[pp]][3]);
                }
            }
        }

        // ---- mask + exp + rowsum ----
        {
            int i0 = w * 16 + g;
            unsigned mwA0 = sM[i0 * 8 + 2 * jt], mwA1 = sM[i0 * 8 + 2 * jt + 1];
            unsigned mwB0 = sM[(i0 + 8) * 8 + 2 * jt], mwB1 = sM[(i0 + 8) * 8 + 2 * jt + 1];
            #pragma unroll
            for (int nt = 0; nt < 8; nt++) {
                unsigned mA = (nt < 4) ? mwA0 : mwA1;
                unsigned mB = (nt < 4) ? mwB0 : mwB1;
                int bb = (nt & 3) * 8 + 2 * t4;
                float* c = sfrag[nt];
                float p0 = ((mA >> bb) & 1u) ? __expf(c[0]) : 0.0f;
                float p1 = ((mA >> (bb + 1)) & 1u) ? __expf(c[1]) : 0.0f;
                float p2 = ((mB >> bb) & 1u) ? __expf(c[2]) : 0.0f;
                float p3 = ((mB >> (bb + 1)) & 1u) ? __expf(c[3]) : 0.0f;
                c[0] = p0; c[1] = p1; c[2] = p2; c[3] = p3;
                lsum[0] += p0 + p1;
                lsum[1] += p2 + p3;
            }
        }

        // ---- P V: terms outer, dn inner -> 4-way accumulator ILP ----
        #pragma unroll
        for (int jkt = 0; jkt < 4; jkt++) {
            uint32_t koff = (uint32_t)(j0 * 2 + jkt * 32) + khB;
            uint32_t vbh[2][4], vbl[2][4];
            #pragma unroll
            for (int dn = 0; dn < 2; dn++) {
                ldm4(vbh[dn], sb + AV_OFF + (vroffh[dn] ^ koff));
                ldm4(vbl[dn], sb + AV_OFF + (vroffl[dn] ^ koff));
            }
            float* cA = sfrag[2 * jkt + 0];
            float* cB = sfrag[2 * jkt + 1];
            uint32_t ahi[4], alo[4];
            ahi[0] = packbf(cA[0], cA[1]);
            ahi[1] = packbf(cA[2], cA[3]);
            ahi[2] = packbf(cB[0], cB[1]);
            ahi[3] = packbf(cB[2], cB[3]);
            alo[0] = packbf(cA[0] - bf_lo(ahi[0]), cA[1] - bf_hi(ahi[0]));
            alo[1] = packbf(cA[2] - bf_lo(ahi[1]), cA[3] - bf_hi(ahi[1]));
            alo[2] = packbf(cB[0] - bf_lo(ahi[2]), cB[1] - bf_hi(ahi[2]));
            alo[3] = packbf(cB[2] - bf_lo(ahi[3]), cB[3] - bf_hi(ahi[3]));
            #pragma unroll
            for (int term = 0; term < 3; term++) {
                const uint32_t* aa = (term == 1) ? alo : ahi;
                const uint32_t (*vb)[4] = (term == 2) ? vbl : vbh;
                #pragma unroll
                for (int dn = 0; dn < 2; dn++) {
                    mma16816(oacc[2 * dn + 0], aa, vb[dn][0], vb[dn][1]);
                    mma16816(oacc[2 * dn + 1], aa, vb[dn][2], vb[dn][3]);
                }
            }
        }
    }

    // ---- normalize + split + store ----
    const size_t rbase = (size_t)(s * B_DIM + b) * N_DIM;
    #pragma unroll
    for (int h2 = 0; h2 < 2; h2++) {
        float l = lsum[h2];
        l += __shfl_xor_sync(0xffffffffu, l, 1);
        l += __shfl_xor_sync(0xffffffffu, l, 2);
        float inv = 1.0f / l;
        int i = w * 16 + g + 8 * h2;
        __nv_bfloat16* o = outsp + (rbase + i) * KS + h * DHEAD;
        #pragma unroll
        for (int nt = 0; nt < 4; nt++) {
            int d = nt * 8 + 2 * t4;
            float v0 = oacc[nt][2 * h2 + 0] * inv;
            float v1 = oacc[nt][2 * h2 + 1] * inv;
            uint32_t uh = packbf(v0, v1);
            uint32_t ul = packbf(v0 - bf_lo(uh), v1 - bf_hi(uh));
            *(uint32_t*)(o + d) = uh;
            *(uint32_t*)(o + 256 + d) = ul;
        }
    }
}

// ---------------------------------------------------------------------------
// Launch
// ---------------------------------------------------------------------------
extern "C" void kernel_launch(void* const* d_in, const int* in_sizes, int n_in,
                              void* d_out, int out_size) {
    const float* x    = (const float*)d_in[0];
    const int*   mask = (const int*)d_in[1];
    const float* Wqkv = (const float*)d_in[2];
    const float* Wout = (const float*)d_in[3];
    const float* bout = (const float*)d_in[4];
    float* out = (float*)d_out;

    float* qkvbuf = nullptr;
    __nv_bfloat16 *abf = nullptr, *wqt = nullptr, *wot = nullptr;
    cudaGetSymbolAddress((void**)&qkvbuf, g_qkv);
    cudaGetSymbolAddress((void**)&abf, g_abf);
    cudaGetSymbolAddress((void**)&wqt, g_wqt);
    cudaGetSymbolAddress((void**)&wot, g_wot);

    cudaFuncSetAttribute(attn_mma_kernel, cudaFuncAttributeMaxDynamicSharedMemorySize,
                         ATTN_SMEM_BYTES);
    cudaFuncSetAttribute(gemm_mma_kernel, cudaFuncAttributeMaxDynamicSharedMemorySize,
                         GEMM_SMEM);

    // Prep
    pack_mask_kernel<<<S_DIM, N_DIM>>>(mask);
    split_w_kernel<<<QKV_COLS, 256>>>(Wqkv, wqt, QKV_COLS);
    split_w_kernel<<<D_MODEL, 256>>>(Wout, wot, D_MODEL);
    split_a_kernel<<<1024, 256>>>(x, abf);

    // 1) QKV projection (tensor cores; q-columns pre-scaled)
    {
        dim3 grid(QKV_COLS / 128, M_TOTAL / 128);
        gemm_mma_kernel<<<grid, 256, GEMM_SMEM>>>(abf, wqt, qkvbuf, nullptr,
                                                  QKV_COLS);
    }
    // 2) Attention (tensor cores; 512 threads; writes split bf16 output)
    {
        dim3 grid(HEADS, B_DIM, S_DIM);
        attn_mma_kernel<<<grid, 512, ATTN_SMEM_BYTES>>>(qkvbuf, abf);
    }
    // 3) Output projection (reads fused-split attn output)
    {
        dim3 grid(D_MODEL / 128, M_TOTAL / 128);
        gemm_mma_kernel<<<grid, 256, GEMM_SMEM>>>(abf, wot, out, bout,
                                                  D_MODEL);
    }
}